// round 4
// baseline (speedup 1.0000x reference)
#include <cuda_runtime.h>

#define NN 100000
#define EE 800000

// ---------------- scratch (device globals) ----------------
__device__ float g_h1[NN * 64];
__device__ float g_h2[NN * 64];
__device__ float g_p[NN * 64];
__device__ float g_g[NN * 128];
__device__ float g_asrc[NN * 2];
__device__ float g_adst[NN * 2];
__device__ float g_Wn[3][4096];
__device__ float g_We[3][320];
__device__ float g_bp[3][64];
__device__ int g_cnt[NN];
__device__ int g_rowptr[NN + 4];
__device__ int g_csr_src[EE];
__device__ int g_csr_eid[EE];
__device__ float g_S[NN * 5];

__device__ __forceinline__ float lrelu(float x) { return x > 0.f ? x : 0.2f * x; }

// ---------------- weight folding (all 3 layers, one launch) ----------------
struct FoldW { const float* w[18]; };

__global__ void fold_kernel(FoldW fw, float* __restrict__ Wn, float* __restrict__ We,
                            float* __restrict__ bp) {
    int L = blockIdx.y;
    const float* wn = fw.w[6 * L + 0];
    const float* bn = fw.w[6 * L + 1];
    const float* we = fw.w[6 * L + 2];
    const float* be = fw.w[6 * L + 3];
    const float* wc = fw.w[6 * L + 4];
    const float* bc = fw.w[6 * L + 5];
    float* WnL = Wn + L * 4096;
    float* WeL = We + L * 320;
    float* bpL = bp + L * 64;
    int t = blockIdx.x * 256 + threadIdx.x;
    if (t >= 4480) return;
    if (t < 4096) {
        int r = t >> 6, c = t & 63;
        float s = 0.f;
        #pragma unroll 8
        for (int k = 0; k < 64; k++) s += wn[r * 64 + k] * wc[k * 64 + c];
        WnL[t] = s;
    } else if (t < 4416) {
        int u = t - 4096;
        int j = u >> 6, c = u & 63;
        float s = 0.f;
        #pragma unroll 8
        for (int k = 0; k < 64; k++) s += we[j * 64 + k] * wc[(64 + k) * 64 + c];
        WeL[u] = s;
    } else {
        int c = t - 4416;
        float s = bc[c];
        #pragma unroll 8
        for (int k = 0; k < 64; k++)
            s += bn[k] * wc[k * 64 + c] + be[k] * wc[(64 + k) * 64 + c];
        bpL[c] = s;
    }
}

// ---------------- zero fill ----------------
__global__ void zero4_kernel(float4* __restrict__ p, int n4) {
    float4 z = make_float4(0.f, 0.f, 0.f, 0.f);
    for (int i = blockIdx.x * blockDim.x + threadIdx.x; i < n4; i += gridDim.x * blockDim.x)
        p[i] = z;
}

// ---------------- CSR build ----------------
__global__ void count_kernel(const int* __restrict__ dst, int* __restrict__ cnt) {
    int i = blockIdx.x * blockDim.x + threadIdx.x;
    if (i * 4 >= EE) return;
    int4 d = ((const int4*)dst)[i];
    atomicAdd(&cnt[d.x], 1);
    atomicAdd(&cnt[d.y], 1);
    atomicAdd(&cnt[d.z], 1);
    atomicAdd(&cnt[d.w], 1);
}

// single-block chunked inclusive scan: rowptr[i+1] = sum cnt[0..i]
__global__ void scan_kernel(const int* __restrict__ cnt, int* __restrict__ rowptr) {
    __shared__ int wsum[32];
    __shared__ int s_carry;
    int t = threadIdx.x;               // 1024 threads
    int lane = t & 31, wid = t >> 5;
    if (t == 0) { s_carry = 0; rowptr[0] = 0; }
    __syncthreads();
    for (int base = 0; base < NN; base += 8192) {
        int v[8];
        int idx0 = base + t * 8;
        #pragma unroll
        for (int j = 0; j < 8; j++) {
            int idx = idx0 + j;
            v[j] = (idx < NN) ? cnt[idx] : 0;
        }
        #pragma unroll
        for (int j = 1; j < 8; j++) v[j] += v[j - 1];
        int tot = v[7];
        int incl = tot;
        #pragma unroll
        for (int o = 1; o < 32; o <<= 1) {
            int u = __shfl_up_sync(0xffffffffu, incl, o);
            if (lane >= o) incl += u;
        }
        if (lane == 31) wsum[wid] = incl;
        __syncthreads();
        if (wid == 0) {
            int x = wsum[lane];
            #pragma unroll
            for (int o = 1; o < 32; o <<= 1) {
                int u = __shfl_up_sync(0xffffffffu, x, o);
                if (lane >= o) x += u;
            }
            wsum[lane] = x;
        }
        __syncthreads();
        int warp_off = (wid == 0) ? 0 : wsum[wid - 1];
        int excl = s_carry + warp_off + (incl - tot);
        #pragma unroll
        for (int j = 0; j < 8; j++) {
            int idx = idx0 + j;
            if (idx < NN) rowptr[idx + 1] = excl + v[j];
        }
        __syncthreads();
        if (t == 0) s_carry += wsum[31];
        __syncthreads();
    }
}

__device__ __forceinline__ void scat1(int d, int s, int e, const int* __restrict__ rowptr,
                                      int* __restrict__ cnt, int* __restrict__ csr_src,
                                      int* __restrict__ csr_eid) {
    int pos = atomicAdd(&cnt[d], -1) - 1;   // countdown: count-1 .. 0
    int slot = rowptr[d] + pos;
    csr_src[slot] = s;
    csr_eid[slot] = e;
}

__global__ void scatter_kernel(const int* __restrict__ src, const int* __restrict__ dst,
                               const int* __restrict__ rowptr, int* __restrict__ cnt,
                               int* __restrict__ csr_src, int* __restrict__ csr_eid) {
    int i = blockIdx.x * blockDim.x + threadIdx.x;
    if (i * 4 >= EE) return;
    int4 d4 = ((const int4*)dst)[i];
    int4 s4 = ((const int4*)src)[i];
    int e = i * 4;
    scat1(d4.x, s4.x, e + 0, rowptr, cnt, csr_src, csr_eid);
    scat1(d4.y, s4.y, e + 1, rowptr, cnt, csr_src, csr_eid);
    scat1(d4.z, s4.z, e + 2, rowptr, cnt, csr_src, csr_eid);
    scat1(d4.w, s4.w, e + 3, rowptr, cnt, csr_src, csr_eid);
}

// per-node edge-attr sums S[n] = sum_{e in-edges} ea[e]  (lane-parallel, no atomics)
__global__ void s_kernel(const int* __restrict__ csr_eid, const int* __restrict__ rowptr,
                         const float* __restrict__ ea, float* __restrict__ S) {
    int n = blockIdx.x * 8 + (threadIdx.x >> 5);
    int lane = threadIdx.x & 31;
    int start = rowptr[n], end = rowptr[n + 1];
    float s0 = 0.f, s1 = 0.f, s2 = 0.f, s3 = 0.f, s4 = 0.f;
    for (int j = start + lane; j < end; j += 32) {
        const float* e = ea + (size_t)csr_eid[j] * 5;
        s0 += e[0]; s1 += e[1]; s2 += e[2]; s3 += e[3]; s4 += e[4];
    }
    #pragma unroll
    for (int o = 16; o; o >>= 1) {
        s0 += __shfl_xor_sync(0xffffffffu, s0, o);
        s1 += __shfl_xor_sync(0xffffffffu, s1, o);
        s2 += __shfl_xor_sync(0xffffffffu, s2, o);
        s3 += __shfl_xor_sync(0xffffffffu, s3, o);
        s4 += __shfl_xor_sync(0xffffffffu, s4, o);
    }
    if (lane == 0) {
        S[n * 5 + 0] = s0; S[n * 5 + 1] = s1; S[n * 5 + 2] = s2;
        S[n * 5 + 3] = s3; S[n * 5 + 4] = s4;
    }
}

// ---------------- dense GEMM: 128x64 tile, 4x8 per thread, optional attn epilogue ----------------
// C[n0:n0+128, c0b:c0b+64] = (relu?)A @ W ; attn mode: also aS/aD head blockIdx.y dots
__global__ __launch_bounds__(256) void gemm128_kernel(
    const float* __restrict__ A, const float* __restrict__ W, float* __restrict__ C,
    int n, int relu, int ldw, int attn,
    const float* __restrict__ attS_g, const float* __restrict__ attD_g,
    float* __restrict__ aS, float* __restrict__ aD) {
    __shared__ float hsT[64 * 128];   // A transposed, XOR-swizzled (row ^ (k&28))
    __shared__ float Ws[64][64];
    int n0 = blockIdx.x << 7;
    int y = blockIdx.y;
    int c0b = y << 6;
    int t = threadIdx.x;
    int tx = t & 7, ty = t >> 3;

    #pragma unroll
    for (int i = 0; i < 4; i++) {
        int idx = t + i * 256;
        int k = idx >> 4;
        int c4 = (idx & 15) << 2;
        *(float4*)&Ws[k][c4] = *(const float4*)(W + (size_t)k * ldw + c0b + c4);
    }
    #pragma unroll
    for (int i = 0; i < 8; i++) {
        int idx = t + i * 256;
        int row = idx >> 4;
        int k4 = (idx & 15) << 2;
        float4 v = make_float4(0.f, 0.f, 0.f, 0.f);
        if (n0 + row < n) v = *(const float4*)(A + (size_t)(n0 + row) * 64 + k4);
        if (relu) {
            v.x = fmaxf(v.x, 0.f); v.y = fmaxf(v.y, 0.f);
            v.z = fmaxf(v.z, 0.f); v.w = fmaxf(v.w, 0.f);
        }
        hsT[(k4 + 0) * 128 + (row ^ ((k4 + 0) & 28))] = v.x;
        hsT[(k4 + 1) * 128 + (row ^ ((k4 + 1) & 28))] = v.y;
        hsT[(k4 + 2) * 128 + (row ^ ((k4 + 2) & 28))] = v.z;
        hsT[(k4 + 3) * 128 + (row ^ ((k4 + 3) & 28))] = v.w;
    }
    __syncthreads();

    int r0 = ty << 2;
    float acc[4][8];
    #pragma unroll
    for (int i = 0; i < 4; i++)
        #pragma unroll
        for (int j = 0; j < 8; j++) acc[i][j] = 0.f;

    #pragma unroll 16
    for (int k = 0; k < 64; k++) {
        float4 a = *(float4*)&hsT[k * 128 + (r0 ^ (k & 28))];
        float4 b0 = *(float4*)&Ws[k][tx * 8];
        float4 b1 = *(float4*)&Ws[k][tx * 8 + 4];
        float av[4] = {a.x, a.y, a.z, a.w};
        float bv[8] = {b0.x, b0.y, b0.z, b0.w, b1.x, b1.y, b1.z, b1.w};
        #pragma unroll
        for (int i = 0; i < 4; i++)
            #pragma unroll
            for (int j = 0; j < 8; j++) acc[i][j] += av[i] * bv[j];
    }

    #pragma unroll
    for (int i = 0; i < 4; i++) {
        int row = n0 + r0 + i;
        if (row < n) {
            *(float4*)(C + (size_t)row * ldw + c0b + tx * 8) =
                make_float4(acc[i][0], acc[i][1], acc[i][2], acc[i][3]);
            *(float4*)(C + (size_t)row * ldw + c0b + tx * 8 + 4) =
                make_float4(acc[i][4], acc[i][5], acc[i][6], acc[i][7]);
        }
    }

    if (attn) {
        float as8[8], ad8[8];
        #pragma unroll
        for (int j = 0; j < 8; j++) {
            as8[j] = attS_g[c0b + tx * 8 + j];
            ad8[j] = attD_g[c0b + tx * 8 + j];
        }
        #pragma unroll
        for (int i = 0; i < 4; i++) {
            float pS = 0.f, pD = 0.f;
            #pragma unroll
            for (int j = 0; j < 8; j++) {
                pS += acc[i][j] * as8[j];
                pD += acc[i][j] * ad8[j];
            }
            #pragma unroll
            for (int o = 1; o < 8; o <<= 1) {
                pS += __shfl_xor_sync(0xffffffffu, pS, o);
                pD += __shfl_xor_sync(0xffffffffu, pD, o);
            }
            int row = n0 + r0 + i;
            if ((t & 7) == 0 && row < n) {
                aS[row * 2 + y] = pS;
                aD[row * 2 + y] = pD;
            }
        }
    }
}

// ---------------- edge aggregation (CSR, warp per node) ----------------
__global__ void agg_kernel(const float* __restrict__ p, const int* __restrict__ csr_src,
                           const int* __restrict__ rowptr, const float* __restrict__ S,
                           const float* __restrict__ We, const float* __restrict__ bp,
                           float* __restrict__ out) {
    __shared__ float sWe[320];
    __shared__ float sbp[64];
    int t = threadIdx.x;
    for (int i = t; i < 384; i += 256) {
        if (i < 320) sWe[i] = We[i];
        else sbp[i - 320] = bp[i - 320];
    }
    __syncthreads();

    int n = blockIdx.x * 8 + (t >> 5);
    int lane = t & 31;
    int start = rowptr[n], end = rowptr[n + 1];
    float s0 = S[n * 5 + 0], s1 = S[n * 5 + 1], s2 = S[n * 5 + 2],
          s3 = S[n * 5 + 3], s4 = S[n * 5 + 4];
    float deg = (float)(end - start);
    int c = lane, c2 = lane + 32;
    float acc0 = deg * sbp[c] + s0 * sWe[c] + s1 * sWe[64 + c] + s2 * sWe[128 + c] +
                 s3 * sWe[192 + c] + s4 * sWe[256 + c];
    float acc1 = deg * sbp[c2] + s0 * sWe[c2] + s1 * sWe[64 + c2] + s2 * sWe[128 + c2] +
                 s3 * sWe[192 + c2] + s4 * sWe[256 + c2];

    for (int base = start; base < end; base += 32) {
        int cnt = min(32, end - base);
        int sl = (lane < cnt) ? csr_src[base + lane] : 0;
        int j = 0;
        for (; j + 1 < cnt; j += 2) {
            int sa = __shfl_sync(0xffffffffu, sl, j);
            int sb = __shfl_sync(0xffffffffu, sl, j + 1);
            const float* pa = p + (size_t)sa * 64;
            const float* pb = p + (size_t)sb * 64;
            acc0 += pa[c] + pb[c];
            acc1 += pa[c2] + pb[c2];
        }
        if (j < cnt) {
            int sa = __shfl_sync(0xffffffffu, sl, j);
            acc0 += p[(size_t)sa * 64 + c];
            acc1 += p[(size_t)sa * 64 + c2];
        }
    }
    out[(size_t)n * 64 + c] = acc0;
    out[(size_t)n * 64 + c2] = acc1;
}

// ---------------- fused GAT: lane-parallel softmax + aggregate + head-mean + bias ----------------
__global__ void gat_kernel(const int* __restrict__ csr_src, const int* __restrict__ rowptr,
                           const float2* __restrict__ aS, const float2* __restrict__ aD,
                           const float* __restrict__ g, const float* __restrict__ b_gat,
                           float* __restrict__ out) {
    int n = blockIdx.x * 8 + (threadIdx.x >> 5);
    int lane = threadIdx.x & 31;
    int start = rowptr[n], end = rowptr[n + 1];
    float2 ad = aD[n];

    // pass 1: lane-parallel max; cache first-chunk values
    float m0 = -1e30f, m1 = -1e30f;
    int s_c = 0;
    float ca0 = 0.f, ca1 = 0.f;
    for (int j = start + lane; j < end; j += 32) {
        int s = csr_src[j];
        float2 as = aS[s];
        float a0 = lrelu(as.x + ad.x), a1 = lrelu(as.y + ad.y);
        if (j - start < 32) { s_c = s; ca0 = a0; ca1 = a1; }
        m0 = fmaxf(m0, a0);
        m1 = fmaxf(m1, a1);
    }
    #pragma unroll
    for (int o = 16; o; o >>= 1) {
        m0 = fmaxf(m0, __shfl_xor_sync(0xffffffffu, m0, o));
        m1 = fmaxf(m1, __shfl_xor_sync(0xffffffffu, m1, o));
    }

    // pass 2: lane-parallel weights, shfl-broadcast gather
    float den0 = 0.f, den1 = 0.f;
    float acc0 = 0.f, acc1 = 0.f, acc2 = 0.f, acc3 = 0.f;
    int deg = end - start;
    for (int base = 0; base < deg; base += 32) {
        int cnt = min(32, deg - base);
        float w0l = 0.f, w1l = 0.f;
        int sl = 0;
        if (lane < cnt) {
            if (base == 0) {
                sl = s_c;
                w0l = __expf(ca0 - m0);
                w1l = __expf(ca1 - m1);
            } else {
                int s = csr_src[start + base + lane];
                float2 as = aS[s];
                sl = s;
                w0l = __expf(lrelu(as.x + ad.x) - m0);
                w1l = __expf(lrelu(as.y + ad.y) - m1);
            }
            den0 += w0l;
            den1 += w1l;
        }
        for (int j = 0; j < cnt; j++) {
            float w0 = __shfl_sync(0xffffffffu, w0l, j);
            float w1 = __shfl_sync(0xffffffffu, w1l, j);
            int s = __shfl_sync(0xffffffffu, sl, j);
            const float* gs = g + (size_t)s * 128;
            acc0 += w0 * gs[lane];
            acc1 += w0 * gs[lane + 32];
            acc2 += w1 * gs[lane + 64];
            acc3 += w1 * gs[lane + 96];
        }
    }
    #pragma unroll
    for (int o = 16; o; o >>= 1) {
        den0 += __shfl_xor_sync(0xffffffffu, den0, o);
        den1 += __shfl_xor_sync(0xffffffffu, den1, o);
    }
    float id0 = 1.f / (den0 + 1e-16f);
    float id1 = 1.f / (den1 + 1e-16f);
    out[(size_t)n * 64 + lane]      = 0.5f * (acc0 * id0 + acc2 * id1) + b_gat[lane];
    out[(size_t)n * 64 + lane + 32] = 0.5f * (acc1 * id0 + acc3 * id1) + b_gat[lane + 32];
}

// ---------------- launch ----------------
extern "C" void kernel_launch(void* const* d_in, const int* in_sizes, int n_in,
                              void* d_out, int out_size) {
    const float* x = (const float*)d_in[0];
    const int* ei = (const int*)d_in[1];
    const float* ea = (const float*)d_in[2];
    const int* src = ei;
    const int* dst = ei + EE;
    FoldW fw;
    for (int i = 0; i < 18; i++) fw.w[i] = (const float*)d_in[3 + i];
    const float* w_gat = (const float*)d_in[21];
    const float* att_src = (const float*)d_in[22];
    const float* att_dst = (const float*)d_in[23];
    const float* b_gat = (const float*)d_in[24];
    float* out = (float*)d_out;

    float *h1, *h2, *p, *gg, *asrc, *adst, *Wn, *We, *bp, *S;
    int *cnt, *rowptr, *csr_src, *csr_eid;
    cudaGetSymbolAddress((void**)&h1, g_h1);
    cudaGetSymbolAddress((void**)&h2, g_h2);
    cudaGetSymbolAddress((void**)&p, g_p);
    cudaGetSymbolAddress((void**)&gg, g_g);
    cudaGetSymbolAddress((void**)&asrc, g_asrc);
    cudaGetSymbolAddress((void**)&adst, g_adst);
    cudaGetSymbolAddress((void**)&Wn, g_Wn);
    cudaGetSymbolAddress((void**)&We, g_We);
    cudaGetSymbolAddress((void**)&bp, g_bp);
    cudaGetSymbolAddress((void**)&cnt, g_cnt);
    cudaGetSymbolAddress((void**)&rowptr, g_rowptr);
    cudaGetSymbolAddress((void**)&csr_src, g_csr_src);
    cudaGetSymbolAddress((void**)&csr_eid, g_csr_eid);
    cudaGetSymbolAddress((void**)&S, g_S);

    const int NB = NN / 8;                 // 12500 warp-per-node blocks
    const int gbx = (NN + 127) / 128;      // 782 gemm row tiles

    // ---- CSR build ----
    zero4_kernel<<<98, 256>>>((float4*)cnt, NN / 4);
    count_kernel<<<(EE / 4 + 255) / 256, 256>>>(dst, cnt);
    scan_kernel<<<1, 1024>>>(cnt, rowptr);
    scatter_kernel<<<(EE / 4 + 255) / 256, 256>>>(src, dst, rowptr, cnt, csr_src, csr_eid);
    s_kernel<<<NB, 256>>>(csr_eid, rowptr, ea, S);

    // ---- fold weights (all layers) ----
    fold_kernel<<<dim3(18, 3), 256>>>(fw, Wn, We, bp);

    // ---- layer 1..3 ----
    gemm128_kernel<<<dim3(gbx, 1), 256>>>(x, Wn + 0 * 4096, p, NN, 0, 64, 0,
                                          nullptr, nullptr, nullptr, nullptr);
    agg_kernel<<<NB, 256>>>(p, csr_src, rowptr, S, We + 0 * 320, bp + 0 * 64, h1);
    gemm128_kernel<<<dim3(gbx, 1), 256>>>(h1, Wn + 1 * 4096, p, NN, 1, 64, 0,
                                          nullptr, nullptr, nullptr, nullptr);
    agg_kernel<<<NB, 256>>>(p, csr_src, rowptr, S, We + 1 * 320, bp + 1 * 64, h2);
    gemm128_kernel<<<dim3(gbx, 1), 256>>>(h2, Wn + 2 * 4096, p, NN, 1, 64, 0,
                                          nullptr, nullptr, nullptr, nullptr);
    agg_kernel<<<NB, 256>>>(p, csr_src, rowptr, S, We + 2 * 320, bp + 2 * 64, h1);

    // ---- GAT projection (attn dots fused into epilogue) ----
    gemm128_kernel<<<dim3(gbx, 2), 256>>>(h1, w_gat, gg, NN, 1, 128, 1,
                                          att_src, att_dst, asrc, adst);
    gat_kernel<<<NB, 256>>>(csr_src, rowptr, (const float2*)asrc, (const float2*)adst,
                            gg, b_gat, out);
}

// round 5
// speedup vs baseline: 1.0443x; 1.0443x over previous
#include <cuda_runtime.h>

#define NN 100000
#define EE 800000

typedef unsigned long long ull;

// ---------------- scratch (device globals) ----------------
__device__ float g_h1[NN * 64];
__device__ float g_h2[NN * 64];
__device__ float g_p[NN * 64];
__device__ float g_g[NN * 128];
__device__ float g_asrc[NN * 2];
__device__ float g_adst[NN * 2];
__device__ float g_Wn[3][4096];
__device__ float g_We[3][320];
__device__ float g_bp[3][64];
__device__ int g_cnt[NN];
__device__ int g_rowptr[NN + 4];
__device__ int g_csr_src[EE];
__device__ float g_S[NN * 5];

__device__ __forceinline__ float lrelu(float x) { return x > 0.f ? x : 0.2f * x; }

// f32x2 packed math (Blackwell): 2 fp32 FMAs per issue slot
__device__ __forceinline__ ull pk2(float x) {
    ull r; asm("mov.b64 %0,{%1,%1};" : "=l"(r) : "f"(x)); return r;
}
__device__ __forceinline__ void fma2(ull& d, ull a, ull b) {
    asm("fma.rn.f32x2 %0,%1,%2,%0;" : "+l"(d) : "l"(a), "l"(b));
}
__device__ __forceinline__ float2 up2(ull v) {
    float2 r; asm("mov.b64 {%0,%1},%2;" : "=f"(r.x), "=f"(r.y) : "l"(v)); return r;
}

// ---------------- weight folding (all 3 layers) ----------------
struct FoldW { const float* w[18]; };

__global__ void fold_kernel(FoldW fw, float* __restrict__ Wn, float* __restrict__ We,
                            float* __restrict__ bp) {
    int L = blockIdx.y;
    const float* wn = fw.w[6 * L + 0];
    const float* bn = fw.w[6 * L + 1];
    const float* we = fw.w[6 * L + 2];
    const float* be = fw.w[6 * L + 3];
    const float* wc = fw.w[6 * L + 4];
    const float* bc = fw.w[6 * L + 5];
    float* WnL = Wn + L * 4096;
    float* WeL = We + L * 320;
    float* bpL = bp + L * 64;
    int t = blockIdx.x * 256 + threadIdx.x;
    if (t >= 4480) return;
    if (t < 4096) {
        int r = t >> 6, c = t & 63;
        float s = 0.f;
        #pragma unroll 8
        for (int k = 0; k < 64; k++) s += wn[r * 64 + k] * wc[k * 64 + c];
        WnL[t] = s;
    } else if (t < 4416) {
        int u = t - 4096;
        int j = u >> 6, c = u & 63;
        float s = 0.f;
        #pragma unroll 8
        for (int k = 0; k < 64; k++) s += we[j * 64 + k] * wc[(64 + k) * 64 + c];
        WeL[u] = s;
    } else {
        int c = t - 4416;
        float s = bc[c];
        #pragma unroll 8
        for (int k = 0; k < 64; k++)
            s += bn[k] * wc[k * 64 + c] + be[k] * wc[(64 + k) * 64 + c];
        bpL[c] = s;
    }
}

// ---------------- zero fill ----------------
__global__ void zero4_kernel(float4* __restrict__ p, int n4) {
    float4 z = make_float4(0.f, 0.f, 0.f, 0.f);
    for (int i = blockIdx.x * blockDim.x + threadIdx.x; i < n4; i += gridDim.x * blockDim.x)
        p[i] = z;
}

// ---------------- CSR build ----------------
__global__ void count_kernel(const int* __restrict__ dst, int* __restrict__ cnt) {
    int i = blockIdx.x * blockDim.x + threadIdx.x;
    if (i * 4 >= EE) return;
    int4 d = ((const int4*)dst)[i];
    atomicAdd(&cnt[d.x], 1);
    atomicAdd(&cnt[d.y], 1);
    atomicAdd(&cnt[d.z], 1);
    atomicAdd(&cnt[d.w], 1);
}

__global__ void scan_kernel(const int* __restrict__ cnt, int* __restrict__ rowptr) {
    __shared__ int wsum[32];
    __shared__ int s_carry;
    int t = threadIdx.x;               // 1024 threads
    int lane = t & 31, wid = t >> 5;
    if (t == 0) { s_carry = 0; rowptr[0] = 0; }
    __syncthreads();
    for (int base = 0; base < NN; base += 8192) {
        int v[8];
        int idx0 = base + t * 8;
        #pragma unroll
        for (int j = 0; j < 8; j++) {
            int idx = idx0 + j;
            v[j] = (idx < NN) ? cnt[idx] : 0;
        }
        #pragma unroll
        for (int j = 1; j < 8; j++) v[j] += v[j - 1];
        int tot = v[7];
        int incl = tot;
        #pragma unroll
        for (int o = 1; o < 32; o <<= 1) {
            int u = __shfl_up_sync(0xffffffffu, incl, o);
            if (lane >= o) incl += u;
        }
        if (lane == 31) wsum[wid] = incl;
        __syncthreads();
        if (wid == 0) {
            int x = wsum[lane];
            #pragma unroll
            for (int o = 1; o < 32; o <<= 1) {
                int u = __shfl_up_sync(0xffffffffu, x, o);
                if (lane >= o) x += u;
            }
            wsum[lane] = x;
        }
        __syncthreads();
        int warp_off = (wid == 0) ? 0 : wsum[wid - 1];
        int excl = s_carry + warp_off + (incl - tot);
        #pragma unroll
        for (int j = 0; j < 8; j++) {
            int idx = idx0 + j;
            if (idx < NN) rowptr[idx + 1] = excl + v[j];
        }
        __syncthreads();
        if (t == 0) s_carry += wsum[31];
        __syncthreads();
    }
}

// scatter: countdown on cnt, write csr_src, fused S accumulation
__device__ __forceinline__ void scat1(int d, int s, int e, const int* __restrict__ rowptr,
                                      int* __restrict__ cnt, int* __restrict__ csr_src,
                                      const float* __restrict__ ea, float* __restrict__ S) {
    int pos = atomicAdd(&cnt[d], -1) - 1;
    csr_src[rowptr[d] + pos] = s;
    const float* eap = ea + (size_t)e * 5;
    #pragma unroll
    for (int k = 0; k < 5; k++) atomicAdd(&S[d * 5 + k], eap[k]);
}

__global__ void scatter_kernel(const int* __restrict__ src, const int* __restrict__ dst,
                               const int* __restrict__ rowptr, int* __restrict__ cnt,
                               int* __restrict__ csr_src, const float* __restrict__ ea,
                               float* __restrict__ S) {
    int i = blockIdx.x * blockDim.x + threadIdx.x;
    if (i * 4 >= EE) return;
    int4 d4 = ((const int4*)dst)[i];
    int4 s4 = ((const int4*)src)[i];
    int e = i * 4;
    scat1(d4.x, s4.x, e + 0, rowptr, cnt, csr_src, ea, S);
    scat1(d4.y, s4.y, e + 1, rowptr, cnt, csr_src, ea, S);
    scat1(d4.z, s4.z, e + 2, rowptr, cnt, csr_src, ea, S);
    scat1(d4.w, s4.w, e + 3, rowptr, cnt, csr_src, ea, S);
}

// ---------------- dense GEMM: 256x64 tile, 8x8/thread, f32x2, A streamed from global ----------------
// C[n0:n0+256, c0b:c0b+64] = (relu?)A @ W ; attn: also head-y attention dots into aS/aD
__global__ __launch_bounds__(256) void gemm_big(
    const float* __restrict__ A, const float* __restrict__ W, float* __restrict__ C,
    int n, int relu, int ldw, int attn,
    const float* __restrict__ attS_g, const float* __restrict__ attD_g,
    float* __restrict__ aS, float* __restrict__ aD) {
    __shared__ float Ws[64][64];   // 16KB: B tile only
    int n0 = blockIdx.x << 8;
    int y = blockIdx.y;
    int c0b = y << 6;
    int t = threadIdx.x;
    int tx = t & 7, ty = t >> 3;

    #pragma unroll
    for (int i = 0; i < 4; i++) {
        int idx = t + i * 256;
        int k = idx >> 4;
        int c4 = (idx & 15) << 2;
        *(float4*)&Ws[k][c4] = *(const float4*)(W + (size_t)k * ldw + c0b + c4);
    }
    __syncthreads();

    int r0 = n0 + ty * 8;
    ull acc[8][4];
    #pragma unroll
    for (int i = 0; i < 8; i++)
        #pragma unroll
        for (int j = 0; j < 4; j++) acc[i][j] = 0ull;

    for (int kc = 0; kc < 64; kc += 4) {
        float4 a[8];
        #pragma unroll
        for (int i = 0; i < 8; i++) {
            int row = r0 + i;
            float4 v = make_float4(0.f, 0.f, 0.f, 0.f);
            if (row < n) v = *(const float4*)(A + (size_t)row * 64 + kc);
            if (relu) {
                v.x = fmaxf(v.x, 0.f); v.y = fmaxf(v.y, 0.f);
                v.z = fmaxf(v.z, 0.f); v.w = fmaxf(v.w, 0.f);
            }
            a[i] = v;
        }
        #pragma unroll
        for (int kk = 0; kk < 4; kk++) {
            const ull* bp = (const ull*)&Ws[kc + kk][tx * 8];
            ull b0 = bp[0], b1 = bp[1], b2 = bp[2], b3 = bp[3];
            #pragma unroll
            for (int i = 0; i < 8; i++) {
                float av = (kk == 0) ? a[i].x : (kk == 1) ? a[i].y : (kk == 2) ? a[i].z : a[i].w;
                ull a2 = pk2(av);
                fma2(acc[i][0], a2, b0);
                fma2(acc[i][1], a2, b1);
                fma2(acc[i][2], a2, b2);
                fma2(acc[i][3], a2, b3);
            }
        }
    }

    float as8[8], ad8[8];
    if (attn) {
        #pragma unroll
        for (int j = 0; j < 8; j++) {
            as8[j] = attS_g[c0b + tx * 8 + j];
            ad8[j] = attD_g[c0b + tx * 8 + j];
        }
    }

    #pragma unroll
    for (int i = 0; i < 8; i++) {
        int row = r0 + i;
        float2 p0 = up2(acc[i][0]), p1 = up2(acc[i][1]);
        float2 p2 = up2(acc[i][2]), p3 = up2(acc[i][3]);
        if (row < n) {
            *(float4*)(C + (size_t)row * ldw + c0b + tx * 8) =
                make_float4(p0.x, p0.y, p1.x, p1.y);
            *(float4*)(C + (size_t)row * ldw + c0b + tx * 8 + 4) =
                make_float4(p2.x, p2.y, p3.x, p3.y);
        }
        if (attn) {
            float pS = p0.x * as8[0] + p0.y * as8[1] + p1.x * as8[2] + p1.y * as8[3] +
                       p2.x * as8[4] + p2.y * as8[5] + p3.x * as8[6] + p3.y * as8[7];
            float pD = p0.x * ad8[0] + p0.y * ad8[1] + p1.x * ad8[2] + p1.y * ad8[3] +
                       p2.x * ad8[4] + p2.y * ad8[5] + p3.x * ad8[6] + p3.y * ad8[7];
            #pragma unroll
            for (int o = 1; o < 8; o <<= 1) {
                pS += __shfl_xor_sync(0xffffffffu, pS, o);
                pD += __shfl_xor_sync(0xffffffffu, pD, o);
            }
            if (tx == 0 && row < n) {
                aS[row * 2 + y] = pS;
                aD[row * 2 + y] = pD;
            }
        }
    }
}

// ---------------- edge aggregation (CSR, warp per node) — R3 proven ----------------
__global__ void agg_kernel(const float* __restrict__ p, const int* __restrict__ csr_src,
                           const int* __restrict__ rowptr, const float* __restrict__ S,
                           const float* __restrict__ We, const float* __restrict__ bp,
                           float* __restrict__ out) {
    __shared__ float sWe[320];
    __shared__ float sbp[64];
    int t = threadIdx.x;
    for (int i = t; i < 384; i += 256) {
        if (i < 320) sWe[i] = We[i];
        else sbp[i - 320] = bp[i - 320];
    }
    __syncthreads();

    int n = blockIdx.x * 8 + (t >> 5);
    int lane = t & 31;
    int start = rowptr[n], end = rowptr[n + 1];
    float s0 = S[n * 5 + 0], s1 = S[n * 5 + 1], s2 = S[n * 5 + 2],
          s3 = S[n * 5 + 3], s4 = S[n * 5 + 4];
    float deg = (float)(end - start);
    int c = lane, c2 = lane + 32;
    float acc0 = deg * sbp[c] + s0 * sWe[c] + s1 * sWe[64 + c] + s2 * sWe[128 + c] +
                 s3 * sWe[192 + c] + s4 * sWe[256 + c];
    float acc1 = deg * sbp[c2] + s0 * sWe[c2] + s1 * sWe[64 + c2] + s2 * sWe[128 + c2] +
                 s3 * sWe[192 + c2] + s4 * sWe[256 + c2];

    int j = start;
    for (; j + 1 < end; j += 2) {
        int sa = csr_src[j], sb = csr_src[j + 1];
        const float* pa = p + (size_t)sa * 64;
        const float* pb = p + (size_t)sb * 64;
        acc0 += pa[c] + pb[c];
        acc1 += pa[c2] + pb[c2];
    }
    if (j < end) {
        int sa = csr_src[j];
        acc0 += p[(size_t)sa * 64 + c];
        acc1 += p[(size_t)sa * 64 + c2];
    }
    out[(size_t)n * 64 + c] = acc0;
    out[(size_t)n * 64 + c2] = acc1;
}

// ---------------- fused GAT — R3 proven ----------------
__global__ void gat_kernel(const int* __restrict__ csr_src, const int* __restrict__ rowptr,
                           const float2* __restrict__ aS, const float2* __restrict__ aD,
                           const float* __restrict__ g, const float* __restrict__ b_gat,
                           float* __restrict__ out) {
    int n = blockIdx.x * 8 + (threadIdx.x >> 5);
    int lane = threadIdx.x & 31;
    int start = rowptr[n], end = rowptr[n + 1];
    float2 ad = aD[n];
    float m0 = -1e30f, m1 = -1e30f;
    for (int j = start; j < end; j++) {
        int s = csr_src[j];
        float2 as = aS[s];
        float a0 = lrelu(as.x + ad.x), a1 = lrelu(as.y + ad.y);
        m0 = fmaxf(m0, a0);
        m1 = fmaxf(m1, a1);
    }
    float acc0 = 0.f, acc1 = 0.f, acc2 = 0.f, acc3 = 0.f, den0 = 0.f, den1 = 0.f;
    for (int j = start; j < end; j++) {
        int s = csr_src[j];
        float2 as = aS[s];
        float a0 = lrelu(as.x + ad.x), a1 = lrelu(as.y + ad.y);
        float w0 = __expf(a0 - m0), w1 = __expf(a1 - m1);
        den0 += w0;
        den1 += w1;
        const float* gs = g + (size_t)s * 128;
        acc0 += w0 * gs[lane];
        acc1 += w0 * gs[lane + 32];
        acc2 += w1 * gs[lane + 64];
        acc3 += w1 * gs[lane + 96];
    }
    float id0 = 1.f / (den0 + 1e-16f);
    float id1 = 1.f / (den1 + 1e-16f);
    out[(size_t)n * 64 + lane]      = 0.5f * (acc0 * id0 + acc2 * id1) + b_gat[lane];
    out[(size_t)n * 64 + lane + 32] = 0.5f * (acc1 * id0 + acc3 * id1) + b_gat[lane + 32];
}

// ---------------- launch ----------------
extern "C" void kernel_launch(void* const* d_in, const int* in_sizes, int n_in,
                              void* d_out, int out_size) {
    const float* x = (const float*)d_in[0];
    const int* ei = (const int*)d_in[1];
    const float* ea = (const float*)d_in[2];
    const int* src = ei;
    const int* dst = ei + EE;
    FoldW fw;
    for (int i = 0; i < 18; i++) fw.w[i] = (const float*)d_in[3 + i];
    const float* w_gat = (const float*)d_in[21];
    const float* att_src = (const float*)d_in[22];
    const float* att_dst = (const float*)d_in[23];
    const float* b_gat = (const float*)d_in[24];
    float* out = (float*)d_out;

    float *h1, *h2, *p, *gg, *asrc, *adst, *Wn, *We, *bp, *S;
    int *cnt, *rowptr, *csr_src;
    cudaGetSymbolAddress((void**)&h1, g_h1);
    cudaGetSymbolAddress((void**)&h2, g_h2);
    cudaGetSymbolAddress((void**)&p, g_p);
    cudaGetSymbolAddress((void**)&gg, g_g);
    cudaGetSymbolAddress((void**)&asrc, g_asrc);
    cudaGetSymbolAddress((void**)&adst, g_adst);
    cudaGetSymbolAddress((void**)&Wn, g_Wn);
    cudaGetSymbolAddress((void**)&We, g_We);
    cudaGetSymbolAddress((void**)&bp, g_bp);
    cudaGetSymbolAddress((void**)&cnt, g_cnt);
    cudaGetSymbolAddress((void**)&rowptr, g_rowptr);
    cudaGetSymbolAddress((void**)&csr_src, g_csr_src);
    cudaGetSymbolAddress((void**)&S, g_S);

    const int NB = NN / 8;                 // 12500 warp-per-node blocks
    const int gbx = (NN + 255) / 256;      // 391 gemm row tiles

    // ---- CSR build ----
    zero4_kernel<<<98, 256>>>((float4*)cnt, NN / 4);
    zero4_kernel<<<489, 256>>>((float4*)S, NN * 5 / 4);
    count_kernel<<<(EE / 4 + 255) / 256, 256>>>(dst, cnt);
    scan_kernel<<<1, 1024>>>(cnt, rowptr);
    scatter_kernel<<<(EE / 4 + 255) / 256, 256>>>(src, dst, rowptr, cnt, csr_src, ea, S);

    // ---- fold weights ----
    fold_kernel<<<dim3(18, 3), 256>>>(fw, Wn, We, bp);

    // ---- layer 1..3 ----
    gemm_big<<<dim3(gbx, 1), 256>>>(x, Wn + 0 * 4096, p, NN, 0, 64, 0,
                                    nullptr, nullptr, nullptr, nullptr);
    agg_kernel<<<NB, 256>>>(p, csr_src, rowptr, S, We + 0 * 320, bp + 0 * 64, h1);
    gemm_big<<<dim3(gbx, 1), 256>>>(h1, Wn + 1 * 4096, p, NN, 1, 64, 0,
                                    nullptr, nullptr, nullptr, nullptr);
    agg_kernel<<<NB, 256>>>(p, csr_src, rowptr, S, We + 1 * 320, bp + 1 * 64, h2);
    gemm_big<<<dim3(gbx, 1), 256>>>(h2, Wn + 2 * 4096, p, NN, 1, 64, 0,
                                    nullptr, nullptr, nullptr, nullptr);
    agg_kernel<<<NB, 256>>>(p, csr_src, rowptr, S, We + 2 * 320, bp + 2 * 64, h1);

    // ---- GAT projection (attn dots fused into epilogue) ----
    gemm_big<<<dim3(gbx, 2), 256>>>(h1, w_gat, gg, NN, 1, 128, 1,
                                    att_src, att_dst, asrc, adst);
    gat_kernel<<<NB, 256>>>(csr_src, rowptr, (const float2*)asrc, (const float2*)adst,
                            gg, b_gat, out);
}

// round 6
// speedup vs baseline: 1.2225x; 1.1707x over previous
#include <cuda_runtime.h>

#define NN 100000
#define EE 800000
#define SCAN_CHUNK 1024
#define SCAN_NB 98   // 98*1024 = 100352 >= NN

typedef unsigned long long ull;

// ---------------- scratch (device globals) ----------------
__device__ float g_h1[NN * 64];
__device__ float g_h2[NN * 64];
__device__ float g_p[NN * 64];
__device__ float g_g[NN * 128];
__device__ float g_asrc[NN * 2];
__device__ float g_adst[NN * 2];
__device__ float g_Wn[3][4096];
__device__ float g_We[3][320];
__device__ float g_bp[3][64];
__device__ int g_cnt[NN];
__device__ int g_rowptr[NN + 4];
__device__ int g_csr_src[EE];
__device__ float g_S[NN * 5];
__device__ int g_bsum[SCAN_NB];
__device__ int g_boff[SCAN_NB];

__device__ __forceinline__ float lrelu(float x) { return x > 0.f ? x : 0.2f * x; }

// f32x2 packed math (Blackwell): 2 fp32 FMAs per issue slot
__device__ __forceinline__ ull pk2(float x) {
    ull r; asm("mov.b64 %0,{%1,%1};" : "=l"(r) : "f"(x)); return r;
}
__device__ __forceinline__ void fma2(ull& d, ull a, ull b) {
    asm("fma.rn.f32x2 %0,%1,%2,%0;" : "+l"(d) : "l"(a), "l"(b));
}
__device__ __forceinline__ float2 up2(ull v) {
    float2 r; asm("mov.b64 {%0,%1},%2;" : "=f"(r.x), "=f"(r.y) : "l"(v)); return r;
}

// ---------------- weight folding (all 3 layers) ----------------
struct FoldW { const float* w[18]; };

__global__ void fold_kernel(FoldW fw, float* __restrict__ Wn, float* __restrict__ We,
                            float* __restrict__ bp) {
    int L = blockIdx.y;
    const float* wn = fw.w[6 * L + 0];
    const float* bn = fw.w[6 * L + 1];
    const float* we = fw.w[6 * L + 2];
    const float* be = fw.w[6 * L + 3];
    const float* wc = fw.w[6 * L + 4];
    const float* bc = fw.w[6 * L + 5];
    float* WnL = Wn + L * 4096;
    float* WeL = We + L * 320;
    float* bpL = bp + L * 64;
    int t = blockIdx.x * 256 + threadIdx.x;
    if (t >= 4480) return;
    if (t < 4096) {
        int r = t >> 6, c = t & 63;
        float s = 0.f;
        #pragma unroll 8
        for (int k = 0; k < 64; k++) s += wn[r * 64 + k] * wc[k * 64 + c];
        WnL[t] = s;
    } else if (t < 4416) {
        int u = t - 4096;
        int j = u >> 6, c = u & 63;
        float s = 0.f;
        #pragma unroll 8
        for (int k = 0; k < 64; k++) s += we[j * 64 + k] * wc[(64 + k) * 64 + c];
        WeL[u] = s;
    } else {
        int c = t - 4416;
        float s = bc[c];
        #pragma unroll 8
        for (int k = 0; k < 64; k++)
            s += bn[k] * wc[k * 64 + c] + be[k] * wc[(64 + k) * 64 + c];
        bpL[c] = s;
    }
}

// ---------------- zero fill ----------------
__global__ void zero4_kernel(float4* __restrict__ p, int n4) {
    float4 z = make_float4(0.f, 0.f, 0.f, 0.f);
    for (int i = blockIdx.x * blockDim.x + threadIdx.x; i < n4; i += gridDim.x * blockDim.x)
        p[i] = z;
}

// ---------------- CSR build ----------------
__global__ void count_kernel(const int* __restrict__ dst, int* __restrict__ cnt) {
    int i = blockIdx.x * blockDim.x + threadIdx.x;
    if (i * 4 >= EE) return;
    int4 d = ((const int4*)dst)[i];
    atomicAdd(&cnt[d.x], 1);
    atomicAdd(&cnt[d.y], 1);
    atomicAdd(&cnt[d.z], 1);
    atomicAdd(&cnt[d.w], 1);
}

// ---- multi-block scan: phase A (per-block totals) ----
__global__ void scan_part(const int* __restrict__ cnt, int* __restrict__ bsum) {
    __shared__ int wsum[8];
    int b = blockIdx.x, t = threadIdx.x;
    int lane = t & 31, wid = t >> 5;
    int idx = b * SCAN_CHUNK + t * 4;
    int s = 0;
    if (idx < NN) {     // NN % 4 == 0, idx aligned -> full int4 valid
        int4 v = *(const int4*)(cnt + idx);
        s = v.x + v.y + v.z + v.w;
    }
    #pragma unroll
    for (int o = 16; o; o >>= 1) s += __shfl_xor_sync(0xffffffffu, s, o);
    if (lane == 0) wsum[wid] = s;
    __syncthreads();
    if (t == 0) {
        int tot = 0;
        #pragma unroll
        for (int w = 0; w < 8; w++) tot += wsum[w];
        bsum[b] = tot;
    }
}

// ---- phase B: exclusive scan of SCAN_NB block totals (one tiny block) ----
__global__ void scan_top(const int* __restrict__ bsum, int* __restrict__ boff) {
    __shared__ int wtot[4];
    int t = threadIdx.x;           // 128 threads
    int lane = t & 31, wid = t >> 5;
    int v = (t < SCAN_NB) ? bsum[t] : 0;
    int incl = v;
    #pragma unroll
    for (int o = 1; o < 32; o <<= 1) {
        int u = __shfl_up_sync(0xffffffffu, incl, o);
        if (lane >= o) incl += u;
    }
    if (lane == 31) wtot[wid] = incl;
    __syncthreads();
    int woff = 0;
    for (int w = 0; w < wid; w++) woff += wtot[w];
    if (t < SCAN_NB) boff[t] = woff + incl - v;   // exclusive
}

// ---- phase C: local scan + block offset -> rowptr ----
__global__ void scan_final(const int* __restrict__ cnt, const int* __restrict__ boff,
                           int* __restrict__ rowptr) {
    __shared__ int wsum[8];
    int b = blockIdx.x, t = threadIdx.x;
    int lane = t & 31, wid = t >> 5;
    int idx = b * SCAN_CHUNK + t * 4;
    int v[4] = {0, 0, 0, 0};
    if (idx < NN) {
        int4 d = *(const int4*)(cnt + idx);
        v[0] = d.x; v[1] = d.y; v[2] = d.z; v[3] = d.w;
    }
    #pragma unroll
    for (int j = 1; j < 4; j++) v[j] += v[j - 1];
    int tot = v[3];
    int incl = tot;
    #pragma unroll
    for (int o = 1; o < 32; o <<= 1) {
        int u = __shfl_up_sync(0xffffffffu, incl, o);
        if (lane >= o) incl += u;
    }
    if (lane == 31) wsum[wid] = incl;
    __syncthreads();
    int woff = 0;
    for (int w = 0; w < wid; w++) woff += wsum[w];
    int excl = boff[b] + woff + incl - tot;
    if (idx < NN) {
        #pragma unroll
        for (int j = 0; j < 4; j++) rowptr[idx + j + 1] = excl + v[j];
    }
    if (b == 0 && t == 0) rowptr[0] = 0;
}

// scatter: countdown on cnt, write csr_src, fused S accumulation
__device__ __forceinline__ void scat1(int d, int s, int e, const int* __restrict__ rowptr,
                                      int* __restrict__ cnt, int* __restrict__ csr_src,
                                      const float* __restrict__ ea, float* __restrict__ S) {
    int pos = atomicAdd(&cnt[d], -1) - 1;
    csr_src[rowptr[d] + pos] = s;
    const float* eap = ea + (size_t)e * 5;
    #pragma unroll
    for (int k = 0; k < 5; k++) atomicAdd(&S[d * 5 + k], eap[k]);
}

__global__ void scatter_kernel(const int* __restrict__ src, const int* __restrict__ dst,
                               const int* __restrict__ rowptr, int* __restrict__ cnt,
                               int* __restrict__ csr_src, const float* __restrict__ ea,
                               float* __restrict__ S) {
    int i = blockIdx.x * blockDim.x + threadIdx.x;
    if (i * 4 >= EE) return;
    int4 d4 = ((const int4*)dst)[i];
    int4 s4 = ((const int4*)src)[i];
    int e = i * 4;
    scat1(d4.x, s4.x, e + 0, rowptr, cnt, csr_src, ea, S);
    scat1(d4.y, s4.y, e + 1, rowptr, cnt, csr_src, ea, S);
    scat1(d4.z, s4.z, e + 2, rowptr, cnt, csr_src, ea, S);
    scat1(d4.w, s4.w, e + 3, rowptr, cnt, csr_src, ea, S);
}

// ---------------- dense GEMM: 256x64 tile, 8x8/thread, f32x2, A streamed from global ----------------
__global__ __launch_bounds__(256) void gemm_big(
    const float* __restrict__ A, const float* __restrict__ W, float* __restrict__ C,
    int n, int relu, int ldw, int attn,
    const float* __restrict__ attS_g, const float* __restrict__ attD_g,
    float* __restrict__ aS, float* __restrict__ aD) {
    __shared__ float Ws[64][64];   // 16KB: B tile only
    int n0 = blockIdx.x << 8;
    int y = blockIdx.y;
    int c0b = y << 6;
    int t = threadIdx.x;
    int tx = t & 7, ty = t >> 3;

    #pragma unroll
    for (int i = 0; i < 4; i++) {
        int idx = t + i * 256;
        int k = idx >> 4;
        int c4 = (idx & 15) << 2;
        *(float4*)&Ws[k][c4] = *(const float4*)(W + (size_t)k * ldw + c0b + c4);
    }
    __syncthreads();

    int r0 = n0 + ty * 8;
    ull acc[8][4];
    #pragma unroll
    for (int i = 0; i < 8; i++)
        #pragma unroll
        for (int j = 0; j < 4; j++) acc[i][j] = 0ull;

    for (int kc = 0; kc < 64; kc += 4) {
        float4 a[8];
        #pragma unroll
        for (int i = 0; i < 8; i++) {
            int row = r0 + i;
            float4 v = make_float4(0.f, 0.f, 0.f, 0.f);
            if (row < n) v = *(const float4*)(A + (size_t)row * 64 + kc);
            if (relu) {
                v.x = fmaxf(v.x, 0.f); v.y = fmaxf(v.y, 0.f);
                v.z = fmaxf(v.z, 0.f); v.w = fmaxf(v.w, 0.f);
            }
            a[i] = v;
        }
        #pragma unroll
        for (int kk = 0; kk < 4; kk++) {
            const ull* bp = (const ull*)&Ws[kc + kk][tx * 8];
            ull b0 = bp[0], b1 = bp[1], b2 = bp[2], b3 = bp[3];
            #pragma unroll
            for (int i = 0; i < 8; i++) {
                float av = (kk == 0) ? a[i].x : (kk == 1) ? a[i].y : (kk == 2) ? a[i].z : a[i].w;
                ull a2 = pk2(av);
                fma2(acc[i][0], a2, b0);
                fma2(acc[i][1], a2, b1);
                fma2(acc[i][2], a2, b2);
                fma2(acc[i][3], a2, b3);
            }
        }
    }

    float as8[8], ad8[8];
    if (attn) {
        #pragma unroll
        for (int j = 0; j < 8; j++) {
            as8[j] = attS_g[c0b + tx * 8 + j];
            ad8[j] = attD_g[c0b + tx * 8 + j];
        }
    }

    #pragma unroll
    for (int i = 0; i < 8; i++) {
        int row = r0 + i;
        float2 p0 = up2(acc[i][0]), p1 = up2(acc[i][1]);
        float2 p2 = up2(acc[i][2]), p3 = up2(acc[i][3]);
        if (row < n) {
            *(float4*)(C + (size_t)row * ldw + c0b + tx * 8) =
                make_float4(p0.x, p0.y, p1.x, p1.y);
            *(float4*)(C + (size_t)row * ldw + c0b + tx * 8 + 4) =
                make_float4(p2.x, p2.y, p3.x, p3.y);
        }
        if (attn) {
            float pS = p0.x * as8[0] + p0.y * as8[1] + p1.x * as8[2] + p1.y * as8[3] +
                       p2.x * as8[4] + p2.y * as8[5] + p3.x * as8[6] + p3.y * as8[7];
            float pD = p0.x * ad8[0] + p0.y * ad8[1] + p1.x * ad8[2] + p1.y * ad8[3] +
                       p2.x * ad8[4] + p2.y * ad8[5] + p3.x * ad8[6] + p3.y * ad8[7];
            #pragma unroll
            for (int o = 1; o < 8; o <<= 1) {
                pS += __shfl_xor_sync(0xffffffffu, pS, o);
                pD += __shfl_xor_sync(0xffffffffu, pD, o);
            }
            if (tx == 0 && row < n) {
                aS[row * 2 + y] = pS;
                aD[row * 2 + y] = pD;
            }
        }
    }
}

// ---------------- edge aggregation (CSR, warp per node) ----------------
__global__ void agg_kernel(const float* __restrict__ p, const int* __restrict__ csr_src,
                           const int* __restrict__ rowptr, const float* __restrict__ S,
                           const float* __restrict__ We, const float* __restrict__ bp,
                           float* __restrict__ out) {
    __shared__ float sWe[320];
    __shared__ float sbp[64];
    int t = threadIdx.x;
    for (int i = t; i < 384; i += 256) {
        if (i < 320) sWe[i] = We[i];
        else sbp[i - 320] = bp[i - 320];
    }
    __syncthreads();

    int n = blockIdx.x * 8 + (t >> 5);
    int lane = t & 31;
    int start = rowptr[n], end = rowptr[n + 1];
    float s0 = S[n * 5 + 0], s1 = S[n * 5 + 1], s2 = S[n * 5 + 2],
          s3 = S[n * 5 + 3], s4 = S[n * 5 + 4];
    float deg = (float)(end - start);
    int c = lane, c2 = lane + 32;
    float acc0 = deg * sbp[c] + s0 * sWe[c] + s1 * sWe[64 + c] + s2 * sWe[128 + c] +
                 s3 * sWe[192 + c] + s4 * sWe[256 + c];
    float acc1 = deg * sbp[c2] + s0 * sWe[c2] + s1 * sWe[64 + c2] + s2 * sWe[128 + c2] +
                 s3 * sWe[192 + c2] + s4 * sWe[256 + c2];

    int j = start;
    for (; j + 1 < end; j += 2) {
        int sa = csr_src[j], sb = csr_src[j + 1];
        const float* pa = p + (size_t)sa * 64;
        const float* pb = p + (size_t)sb * 64;
        acc0 += pa[c] + pb[c];
        acc1 += pa[c2] + pb[c2];
    }
    if (j < end) {
        int sa = csr_src[j];
        acc0 += p[(size_t)sa * 64 + c];
        acc1 += p[(size_t)sa * 64 + c2];
    }
    out[(size_t)n * 64 + c] = acc0;
    out[(size_t)n * 64 + c2] = acc1;
}

// ---------------- fused GAT ----------------
__global__ void gat_kernel(const int* __restrict__ csr_src, const int* __restrict__ rowptr,
                           const float2* __restrict__ aS, const float2* __restrict__ aD,
                           const float* __restrict__ g, const float* __restrict__ b_gat,
                           float* __restrict__ out) {
    int n = blockIdx.x * 8 + (threadIdx.x >> 5);
    int lane = threadIdx.x & 31;
    int start = rowptr[n], end = rowptr[n + 1];
    float2 ad = aD[n];
    float m0 = -1e30f, m1 = -1e30f;
    for (int j = start; j < end; j++) {
        int s = csr_src[j];
        float2 as = aS[s];
        float a0 = lrelu(as.x + ad.x), a1 = lrelu(as.y + ad.y);
        m0 = fmaxf(m0, a0);
        m1 = fmaxf(m1, a1);
    }
    float acc0 = 0.f, acc1 = 0.f, acc2 = 0.f, acc3 = 0.f, den0 = 0.f, den1 = 0.f;
    for (int j = start; j < end; j++) {
        int s = csr_src[j];
        float2 as = aS[s];
        float a0 = lrelu(as.x + ad.x), a1 = lrelu(as.y + ad.y);
        float w0 = __expf(a0 - m0), w1 = __expf(a1 - m1);
        den0 += w0;
        den1 += w1;
        const float* gs = g + (size_t)s * 128;
        acc0 += w0 * gs[lane];
        acc1 += w0 * gs[lane + 32];
        acc2 += w1 * gs[lane + 64];
        acc3 += w1 * gs[lane + 96];
    }
    float id0 = 1.f / (den0 + 1e-16f);
    float id1 = 1.f / (den1 + 1e-16f);
    out[(size_t)n * 64 + lane]      = 0.5f * (acc0 * id0 + acc2 * id1) + b_gat[lane];
    out[(size_t)n * 64 + lane + 32] = 0.5f * (acc1 * id0 + acc3 * id1) + b_gat[lane + 32];
}

// ---------------- launch ----------------
extern "C" void kernel_launch(void* const* d_in, const int* in_sizes, int n_in,
                              void* d_out, int out_size) {
    const float* x = (const float*)d_in[0];
    const int* ei = (const int*)d_in[1];
    const float* ea = (const float*)d_in[2];
    const int* src = ei;
    const int* dst = ei + EE;
    FoldW fw;
    for (int i = 0; i < 18; i++) fw.w[i] = (const float*)d_in[3 + i];
    const float* w_gat = (const float*)d_in[21];
    const float* att_src = (const float*)d_in[22];
    const float* att_dst = (const float*)d_in[23];
    const float* b_gat = (const float*)d_in[24];
    float* out = (float*)d_out;

    float *h1, *h2, *p, *gg, *asrc, *adst, *Wn, *We, *bp, *S;
    int *cnt, *rowptr, *csr_src, *bsum, *boff;
    cudaGetSymbolAddress((void**)&h1, g_h1);
    cudaGetSymbolAddress((void**)&h2, g_h2);
    cudaGetSymbolAddress((void**)&p, g_p);
    cudaGetSymbolAddress((void**)&gg, g_g);
    cudaGetSymbolAddress((void**)&asrc, g_asrc);
    cudaGetSymbolAddress((void**)&adst, g_adst);
    cudaGetSymbolAddress((void**)&Wn, g_Wn);
    cudaGetSymbolAddress((void**)&We, g_We);
    cudaGetSymbolAddress((void**)&bp, g_bp);
    cudaGetSymbolAddress((void**)&cnt, g_cnt);
    cudaGetSymbolAddress((void**)&rowptr, g_rowptr);
    cudaGetSymbolAddress((void**)&csr_src, g_csr_src);
    cudaGetSymbolAddress((void**)&S, g_S);
    cudaGetSymbolAddress((void**)&bsum, g_bsum);
    cudaGetSymbolAddress((void**)&boff, g_boff);

    const int NB = NN / 8;                 // 12500 warp-per-node blocks
    const int gbx = (NN + 255) / 256;      // 391 gemm row tiles

    // ---- CSR build ----
    zero4_kernel<<<98, 256>>>((float4*)cnt, NN / 4);
    zero4_kernel<<<489, 256>>>((float4*)S, NN * 5 / 4);
    count_kernel<<<(EE / 4 + 255) / 256, 256>>>(dst, cnt);
    scan_part<<<SCAN_NB, 256>>>(cnt, bsum);
    scan_top<<<1, 128>>>(bsum, boff);
    scan_final<<<SCAN_NB, 256>>>(cnt, boff, rowptr);
    scatter_kernel<<<(EE / 4 + 255) / 256, 256>>>(src, dst, rowptr, cnt, csr_src, ea, S);

    // ---- fold weights ----
    fold_kernel<<<dim3(18, 3), 256>>>(fw, Wn, We, bp);

    // ---- layer 1..3 ----
    gemm_big<<<dim3(gbx, 1), 256>>>(x, Wn + 0 * 4096, p, NN, 0, 64, 0,
                                    nullptr, nullptr, nullptr, nullptr);
    agg_kernel<<<NB, 256>>>(p, csr_src, rowptr, S, We + 0 * 320, bp + 0 * 64, h1);
    gemm_big<<<dim3(gbx, 1), 256>>>(h1, Wn + 1 * 4096, p, NN, 1, 64, 0,
                                    nullptr, nullptr, nullptr, nullptr);
    agg_kernel<<<NB, 256>>>(p, csr_src, rowptr, S, We + 1 * 320, bp + 1 * 64, h2);
    gemm_big<<<dim3(gbx, 1), 256>>>(h2, Wn + 2 * 4096, p, NN, 1, 64, 0,
                                    nullptr, nullptr, nullptr, nullptr);
    agg_kernel<<<NB, 256>>>(p, csr_src, rowptr, S, We + 2 * 320, bp + 2 * 64, h1);

    // ---- GAT projection (attn dots fused into epilogue) ----
    gemm_big<<<dim3(gbx, 2), 256>>>(h1, w_gat, gg, NN, 1, 128, 1,
                                    att_src, att_dst, asrc, adst);
    gat_kernel<<<NB, 256>>>(csr_src, rowptr, (const float2*)asrc, (const float2*)adst,
                            gg, b_gat, out);
}